// round 12
// baseline (speedup 1.0000x reference)
#include <cuda_runtime.h>
#include <math.h>

// Problem constants (fixed by the dataset's setup_inputs)
#define BN   1000      // rois per image
#define NPAD 1024      // slot count per image (>= BN)
#define CC   81        // classes
#define KK   100       // max detections
#define FF   1024      // feature dim
#define META_STRIDE (12 + CC)

#define MIN_CONF 0.7f
#define NMS_THR  0.3f

#define RPC    8       // rois per refine CTA (one per warp)
#define NRBLK  ((BN + RPC - 1) / RPC)         // 125
#define KV_INVALID_HI 0xFFFFFFFFu             // valid kv_hi < 0x80000000

// scratch slot: 8 floats per (image, roi):
//   [0]=kv_hi bits, [1]=roi idx bits, [2]=score, [3]=cls bits, [4..7]=box
// located at feat_out + b*KK*FF + 4 + roi*8  (consumed by nms_kernel
// before any conflicting write; overwritten by gather at the end)
#define SCRATCH_OFF 4

// order-preserving float -> uint32 (ascending)
__device__ __forceinline__ unsigned int float_orderable(float f) {
    unsigned int u = __float_as_uint(f);
    return u ^ ((u >> 31) ? 0xFFFFFFFFu : 0x80000000u);
}

// =====================================================================
// K1: refine. grid = (125, B), 256 threads = 8 warps, one roi per warp.
// Coalesced 32-lane loads of the 81 class probs + shfl argmax
// (max value, min index == first-max). The roi box + window loads are
// hoisted BEFORE the reduce (independent of its result) so their
// latency overlaps the shfl chain. Lane 0 decodes/clips/writes slot.
// =====================================================================
__global__ __launch_bounds__(256)
void refine_kernel(const float* __restrict__ rois,
                   const float* __restrict__ probs,
                   const float* __restrict__ deltas,
                   const float* __restrict__ meta,
                   float* __restrict__ feat_out)
{
    const int b    = blockIdx.y;
    const int i    = blockIdx.x * RPC + (threadIdx.x >> 5);
    const int lane = threadIdx.x & 31;
    if (i >= BN) return;

    const size_t gi = (size_t)b * BN + i;
    const float* pr = probs + gi * CC;

    // lanes cover classes lane, lane+32, lane+64 (coalesced)
    float v0 = pr[lane];
    float v1 = pr[lane + 32];                       // lane+32 <= 63 < 81
    float v2 = (lane + 64 < CC) ? pr[lane + 64] : -1.0f;

    // hoisted independent loads (overlap the reduce): roi box + window
    float4 rr;
    float wy1, wx1, wy2, wx2;
    if (lane == 0) {
        rr = *(const float4*)(rois + gi * 4);
        const float sy = meta[4] - 1.0f;
        const float sx = meta[5] - 1.0f;
        wy1 =  meta[(size_t)b * META_STRIDE + 7]          / sy;
        wx1 =  meta[(size_t)b * META_STRIDE + 8]          / sx;
        wy2 = (meta[(size_t)b * META_STRIDE + 9] - 1.0f)  / sy;
        wx2 = (meta[(size_t)b * META_STRIDE + 10] - 1.0f) / sx;
    }

    float bv = v0; int bc = lane;
    if (v1 > bv) { bv = v1; bc = lane + 32; }
    if (v2 > bv) { bv = v2; bc = lane + 64; }
    #pragma unroll
    for (int off = 16; off > 0; off >>= 1) {
        const float ov = __shfl_xor_sync(0xffffffffu, bv, off);
        const int   oc = __shfl_xor_sync(0xffffffffu, bc, off);
        if (ov > bv || (ov == bv && oc < bc)) { bv = ov; bc = oc; }
    }

    if (lane == 0) {
        float* scratch = feat_out + (size_t)b * KK * FF + SCRATCH_OFF;
        float2* slot = (float2*)(scratch + (size_t)i * 8);
        if (bc > 0 && bv >= MIN_CONF) {
            const float4 dl = *(const float4*)(deltas + (gi * CC + bc) * 4);
            const float dy = dl.x * 0.1f;
            const float dx = dl.y * 0.1f;
            const float dh = dl.z * 0.2f;
            const float dw = dl.w * 0.2f;

            float y1 = rr.x, x1 = rr.y, y2 = rr.z, x2 = rr.w;
            const float h0 = y2 - y1, w0 = x2 - x1;
            const float cy = y1 + 0.5f * h0 + dy * h0;
            const float cx = x1 + 0.5f * w0 + dx * w0;
            const float hh = h0 * expf(dh);
            const float ww = w0 * expf(dw);
            y1 = cy - 0.5f * hh;
            x1 = cx - 0.5f * ww;
            y2 = y1 + hh;
            x2 = x1 + ww;
            y1 = fminf(fmaxf(y1, wy1), wy2);
            x1 = fminf(fmaxf(x1, wx1), wx2);
            y2 = fminf(fmaxf(y2, wy1), wy2);
            x2 = fminf(fmaxf(x2, wx1), wx2);

            slot[0] = make_float2(__uint_as_float(float_orderable(-bv)),
                                  __uint_as_float((unsigned int)i));
            slot[1] = make_float2(bv, __int_as_float(bc));
            slot[2] = make_float2(y1, x1);
            slot[3] = make_float2(y2, x2);
        } else {
            slot[0] = make_float2(__uint_as_float(KV_INVALID_HI), 0.0f);
        }
    }
}

// =====================================================================
// K2: per-image NMS. grid = B, 1024 threads. Loads scratch slots,
// compacts valid candidates, resolves ordering by counting packed-kv
// comparisons (== stable argsort of reference), runs warp-per-class
// greedy NMS, writes det rows + gather index into feat row slot 0.
// =====================================================================
__global__ __launch_bounds__(NPAD)
void nms_kernel(float* __restrict__ det_out,
                float* __restrict__ feat_out)
{
    __shared__ unsigned long long c_kv[NPAD];
    __shared__ float4 c_box[NPAD];
    __shared__ float  c_score[NPAD];
    __shared__ int    c_cls[NPAD];
    __shared__ int    c_wr[NPAD];
    __shared__ int    c_list[NPAD];
    __shared__ unsigned char s_kept[NPAD];
    __shared__ int    s_ccnt[CC], s_cst[CC];
    __shared__ int    s_nv;

    const int b    = blockIdx.x;
    const int tid  = threadIdx.x;
    const int wid  = tid >> 5;
    const int lane = tid & 31;

    if (tid == 0) s_nv = 0;
    for (int c = tid; c < CC; c += NPAD) s_ccnt[c] = 0;
    s_kept[tid] = 0;
    __syncthreads();

    // ---- load scratch slots, compact valid candidates ----
    const float* scratch = feat_out + (size_t)b * KK * FF + SCRATCH_OFF;
    if (tid < BN) {
        const float2* slot = (const float2*)(scratch + (size_t)tid * 8);
        const float2 s0 = slot[0];
        const unsigned int kv_hi = __float_as_uint(s0.x);
        if (kv_hi != KV_INVALID_HI) {
            const float2 s1 = slot[1];
            const float2 s2 = slot[2];
            const float2 s3 = slot[3];
            const int t = atomicAdd(&s_nv, 1);
            c_kv[t]    = ((unsigned long long)kv_hi << 32)
                         | __float_as_uint(s0.y);
            c_score[t] = s1.x;
            c_cls[t]   = __float_as_int(s1.y);
            c_box[t]   = make_float4(s2.x, s2.y, s3.x, s3.y);
        }
    }
    __syncthreads();
    const int V = s_nv;

    // ---- within-class rank by counting ----
    for (int t = tid; t < V; t += NPAD) {
        const unsigned long long kv = c_kv[t];
        const int c = c_cls[t];
        int r = 0;
        for (int q = 0; q < V; q++)
            r += (c_cls[q] == c) && (c_kv[q] < kv);
        c_wr[t] = r;
        atomicAdd(&s_ccnt[c], 1);
    }
    __syncthreads();

    // ---- class prefix + scatter into per-class lists ----
    if (tid == 0) {
        int acc = 0;
        for (int c = 0; c < CC; c++) { s_cst[c] = acc; acc += s_ccnt[c]; }
    }
    __syncthreads();
    for (int t = tid; t < V; t += NPAD)
        c_list[s_cst[c_cls[t]] + c_wr[t]] = t;
    __syncthreads();

    // ---- per-class greedy NMS, one warp per class ----
    for (int c = wid; c < CC; c += 32) {
        const int n = s_ccnt[c];
        if (n == 0) continue;
        const int base = s_cst[c];
        int kc = 0;
        for (int t = 0; t < n; t++) {
            const int s = c_list[base + t];
            const float4 bx = c_box[s];
            const float ca = (bx.z - bx.x) * (bx.w - bx.y);

            bool sup = false;
            for (int q = lane; q < t; q += 32) {
                const int s2 = c_list[base + q];
                if (s_kept[s2]) {
                    const float4 b2 = c_box[s2];
                    const float yy1 = fmaxf(bx.x, b2.x);
                    const float xx1 = fmaxf(bx.y, b2.y);
                    const float yy2 = fminf(bx.z, b2.z);
                    const float xx2 = fminf(bx.w, b2.w);
                    const float inter = fmaxf(yy2 - yy1, 0.0f) * fmaxf(xx2 - xx1, 0.0f);
                    const float a2  = (b2.z - b2.x) * (b2.w - b2.y);
                    const float uni = ca + a2 - inter;
                    if (inter / fmaxf(uni, 1e-8f) > NMS_THR) sup = true;
                }
            }
            if (!__any_sync(0xffffffffu, sup)) {
                if (lane == 0) s_kept[s] = 1;
                kc++;
                if (kc == KK) break;    // class quota full
            }
            __syncwarp();
        }
    }
    __syncthreads();

    // ---- zero-fill all K output rows ----
    for (int k = tid; k < KK; k += NPAD) {
        const size_t bk = (size_t)b * KK + k;
        float* o = det_out + bk * 6;
        o[0] = 0.0f; o[1] = 0.0f; o[2] = 0.0f;
        o[3] = 0.0f; o[4] = 0.0f; o[5] = 0.0f;
        feat_out[bk * FF] = __int_as_float(-1);
    }
    __syncthreads();

    // ---- global kept-rank by counting; write kept rows ----
    for (int t = tid; t < V; t += NPAD) {
        if (!s_kept[t]) continue;
        const unsigned long long kv = c_kv[t];
        int r = 0;
        for (int q = 0; q < V; q++)
            r += s_kept[q] && (c_kv[q] < kv);
        if (r < KK) {
            const size_t bk = (size_t)b * KK + r;
            const float4 bx = c_box[t];
            float* o = det_out + bk * 6;
            o[0] = bx.x;
            o[1] = bx.y;
            o[2] = bx.z;
            o[3] = bx.w;
            o[4] = (float)c_cls[t];
            o[5] = c_score[t];
            feat_out[bk * FF] = __int_as_float((int)(kv & 0xFFFFFFFFu));
        }
    }
}

// =====================================================================
// K3: feature gather, one WARP per output row (no block barriers).
// Lane 0 loads the smuggled roi index, shfl-broadcasts it, then the
// 32 lanes copy 256 float4s (8 each, deep MLP) or zero-fill.
// grid = B*KK/8 CTAs x 256 threads.
// =====================================================================
__global__ __launch_bounds__(256)
void feat_gather_kernel(const float* __restrict__ obj_feat,
                        float* __restrict__ feat_out)
{
    const int warp = threadIdx.x >> 5;
    const int lane = threadIdx.x & 31;
    const int bk   = blockIdx.x * 8 + warp;   // b*KK + k
    const int b    = bk / KK;

    float* dst = feat_out + (size_t)bk * FF;
    int j = 0;
    if (lane == 0) j = __float_as_int(dst[0]);
    j = __shfl_sync(0xffffffffu, j, 0);

    float4* d4 = (float4*)dst;
    if (j >= 0) {
        const float4* s4 = (const float4*)(obj_feat + ((size_t)b * BN + j) * FF);
        #pragma unroll
        for (int r = 0; r < 8; r++)
            d4[lane + 32 * r] = s4[lane + 32 * r];
    } else {
        const float4 z = make_float4(0.0f, 0.0f, 0.0f, 0.0f);
        #pragma unroll
        for (int r = 0; r < 8; r++)
            d4[lane + 32 * r] = z;
    }
}

extern "C" void kernel_launch(void* const* d_in, const int* in_sizes, int n_in,
                              void* d_out, int out_size)
{
    const float* rois     = (const float*)d_in[0];
    const float* fpnclass = (const float*)d_in[1];
    const float* fpnbbox  = (const float*)d_in[2];
    const float* objfeat  = (const float*)d_in[3];
    const float* meta     = (const float*)d_in[4];

    const int B = in_sizes[0] / (BN * 4);

    float* det_out  = (float*)d_out;                         // (B, K, 6)
    float* feat_out = (float*)d_out + (size_t)B * KK * 6;    // (B, K, 1, 1, F)

    dim3 g1(NRBLK, B);
    refine_kernel<<<g1, 256>>>(rois, fpnclass, fpnbbox, meta, feat_out);
    nms_kernel<<<B, NPAD>>>(det_out, feat_out);
    feat_gather_kernel<<<(B * KK) / 8, 256>>>(objfeat, feat_out);
}

// round 15
// speedup vs baseline: 1.0078x; 1.0078x over previous
#include <cuda_runtime.h>
#include <math.h>

// Problem constants (fixed by the dataset's setup_inputs)
#define BN   1000      // rois per image
#define NPAD 1024      // slot count per image (>= BN)
#define CC   81        // classes
#define KK   100       // max detections
#define FF   1024      // feature dim
#define META_STRIDE (12 + CC)

#define MIN_CONF 0.7f
#define NMS_THR  0.3f

#define RCHUNK 64                              // rois per refine CTA
#define NRBLK  ((BN + RCHUNK - 1) / RCHUNK)    // 16
#define CH_FLOATS (RCHUNK * CC)                // 5184 (16B-aligned chunks)
#define KV_INVALID_HI 0xFFFFFFFFu              // valid kv_hi < 0x80000000

// scratch slot: 8 floats per (image, roi):
//   [0]=kv_hi bits, [1]=roi idx bits, [2]=score, [3]=cls bits, [4..7]=box
// located at feat_out + b*KK*FF + 4 + roi*8  (consumed by nms_kernel
// before any conflicting write; overwritten by gather at the end)
#define SCRATCH_OFF 4

// order-preserving float -> uint32 (ascending)
__device__ __forceinline__ unsigned int float_orderable(float f) {
    unsigned int u = __float_as_uint(f);
    return u ^ ((u >> 31) ? 0xFFFFFFFFu : 0x80000000u);
}

// =====================================================================
// K1: refine. grid = (16, B), 256 threads. Stage 64 contiguous roi
// rows of probs (dense, 16B-aligned -> float4 coalesced) into shared,
// then 8 warps x 8 rois: argmax from shared (conflict-free) + shfl
// reduce (max value, min index == first-max); lane 0 decodes/clips and
// writes the 8-float scratch slot.
// =====================================================================
__global__ __launch_bounds__(256)
void refine_kernel(const float* __restrict__ rois,
                   const float* __restrict__ probs,
                   const float* __restrict__ deltas,
                   const float* __restrict__ meta,
                   float* __restrict__ feat_out)
{
    __shared__ __align__(16) float buf[CH_FLOATS];

    const int b    = blockIdx.y;
    const int i0   = blockIdx.x * RCHUNK;
    const int cnt  = (BN - i0 < RCHUNK) ? BN - i0 : RCHUNK;   // 64 or 40
    const int tid  = threadIdx.x;
    const int wid  = tid >> 5;
    const int lane = tid & 31;

    // ---- stage: dense float4 copy of cnt*CC floats ----
    // start float index (b*BN + i0)*CC is divisible by 4 -> 16B aligned
    const float4* src4 = (const float4*)(probs + ((size_t)b * BN + i0) * CC);
    const int nv4 = (cnt * CC) >> 2;          // 1296 or 810
    for (int v = tid; v < nv4; v += 256)
        ((float4*)buf)[v] = src4[v];
    __syncthreads();

    // ---- warp-per-roi argmax from shared ----
    for (int r = wid; r < cnt; r += 8) {
        const float* pr = buf + r * CC;
        float v0 = pr[lane];
        float v1 = pr[lane + 32];
        float v2 = (lane + 64 < CC) ? pr[lane + 64] : -1.0f;

        float bv = v0; int bc = lane;
        if (v1 > bv) { bv = v1; bc = lane + 32; }
        if (v2 > bv) { bv = v2; bc = lane + 64; }
        #pragma unroll
        for (int off = 16; off > 0; off >>= 1) {
            const float ov = __shfl_xor_sync(0xffffffffu, bv, off);
            const int   oc = __shfl_xor_sync(0xffffffffu, bc, off);
            if (ov > bv || (ov == bv && oc < bc)) { bv = ov; bc = oc; }
        }

        if (lane == 0) {
            const int i = i0 + r;
            const size_t gi = (size_t)b * BN + i;
            float* scratch = feat_out + (size_t)b * KK * FF + SCRATCH_OFF;
            float2* slot = (float2*)(scratch + (size_t)i * 8);
            if (bc > 0 && bv >= MIN_CONF) {
                const float sy = meta[4] - 1.0f;
                const float sx = meta[5] - 1.0f;
                const float wy1 =  meta[(size_t)b * META_STRIDE + 7]          / sy;
                const float wx1 =  meta[(size_t)b * META_STRIDE + 8]          / sx;
                const float wy2 = (meta[(size_t)b * META_STRIDE + 9] - 1.0f)  / sy;
                const float wx2 = (meta[(size_t)b * META_STRIDE + 10] - 1.0f) / sx;

                const float4 dl = *(const float4*)(deltas + (gi * CC + bc) * 4);
                const float dy = dl.x * 0.1f;
                const float dx = dl.y * 0.1f;
                const float dh = dl.z * 0.2f;
                const float dw = dl.w * 0.2f;

                const float4 rr = *(const float4*)(rois + gi * 4);
                float y1 = rr.x, x1 = rr.y, y2 = rr.z, x2 = rr.w;
                const float h0 = y2 - y1, w0 = x2 - x1;
                const float cy = y1 + 0.5f * h0 + dy * h0;
                const float cx = x1 + 0.5f * w0 + dx * w0;
                const float hh = h0 * expf(dh);
                const float ww = w0 * expf(dw);
                y1 = cy - 0.5f * hh;
                x1 = cx - 0.5f * ww;
                y2 = y1 + hh;
                x2 = x1 + ww;
                y1 = fminf(fmaxf(y1, wy1), wy2);
                x1 = fminf(fmaxf(x1, wx1), wx2);
                y2 = fminf(fmaxf(y2, wy1), wy2);
                x2 = fminf(fmaxf(x2, wx1), wx2);

                slot[0] = make_float2(__uint_as_float(float_orderable(-bv)),
                                      __uint_as_float((unsigned int)i));
                slot[1] = make_float2(bv, __int_as_float(bc));
                slot[2] = make_float2(y1, x1);
                slot[3] = make_float2(y2, x2);
            } else {
                slot[0] = make_float2(__uint_as_float(KV_INVALID_HI), 0.0f);
            }
        }
    }
}

// =====================================================================
// K2: per-image NMS. grid = B, 1024 threads. Loads scratch slots,
// compacts valid candidates, resolves ordering by counting packed-kv
// comparisons (== stable argsort of reference), runs warp-per-class
// greedy NMS, writes det rows + gather index into feat row slot 0.
// =====================================================================
__global__ __launch_bounds__(NPAD)
void nms_kernel(float* __restrict__ det_out,
                float* __restrict__ feat_out)
{
    __shared__ unsigned long long c_kv[NPAD];
    __shared__ float4 c_box[NPAD];
    __shared__ float  c_score[NPAD];
    __shared__ int    c_cls[NPAD];
    __shared__ int    c_wr[NPAD];
    __shared__ int    c_list[NPAD];
    __shared__ unsigned char s_kept[NPAD];
    __shared__ int    s_ccnt[CC], s_cst[CC];
    __shared__ int    s_nv;

    const int b    = blockIdx.x;
    const int tid  = threadIdx.x;
    const int wid  = tid >> 5;
    const int lane = tid & 31;

    if (tid == 0) s_nv = 0;
    for (int c = tid; c < CC; c += NPAD) s_ccnt[c] = 0;
    s_kept[tid] = 0;
    __syncthreads();

    // ---- load scratch slots, compact valid candidates ----
    const float* scratch = feat_out + (size_t)b * KK * FF + SCRATCH_OFF;
    if (tid < BN) {
        const float2* slot = (const float2*)(scratch + (size_t)tid * 8);
        const float2 s0 = slot[0];
        const unsigned int kv_hi = __float_as_uint(s0.x);
        if (kv_hi != KV_INVALID_HI) {
            const float2 s1 = slot[1];
            const float2 s2 = slot[2];
            const float2 s3 = slot[3];
            const int t = atomicAdd(&s_nv, 1);
            c_kv[t]    = ((unsigned long long)kv_hi << 32)
                         | __float_as_uint(s0.y);
            c_score[t] = s1.x;
            c_cls[t]   = __float_as_int(s1.y);
            c_box[t]   = make_float4(s2.x, s2.y, s3.x, s3.y);
        }
    }
    __syncthreads();
    const int V = s_nv;

    // ---- within-class rank by counting ----
    for (int t = tid; t < V; t += NPAD) {
        const unsigned long long kv = c_kv[t];
        const int c = c_cls[t];
        int r = 0;
        for (int q = 0; q < V; q++)
            r += (c_cls[q] == c) && (c_kv[q] < kv);
        c_wr[t] = r;
        atomicAdd(&s_ccnt[c], 1);
    }
    __syncthreads();

    // ---- class prefix + scatter into per-class lists ----
    if (tid == 0) {
        int acc = 0;
        for (int c = 0; c < CC; c++) { s_cst[c] = acc; acc += s_ccnt[c]; }
    }
    __syncthreads();
    for (int t = tid; t < V; t += NPAD)
        c_list[s_cst[c_cls[t]] + c_wr[t]] = t;
    __syncthreads();

    // ---- per-class greedy NMS, one warp per class ----
    for (int c = wid; c < CC; c += 32) {
        const int n = s_ccnt[c];
        if (n == 0) continue;
        const int base = s_cst[c];
        int kc = 0;
        for (int t = 0; t < n; t++) {
            const int s = c_list[base + t];
            const float4 bx = c_box[s];
            const float ca = (bx.z - bx.x) * (bx.w - bx.y);

            bool sup = false;
            for (int q = lane; q < t; q += 32) {
                const int s2 = c_list[base + q];
                if (s_kept[s2]) {
                    const float4 b2 = c_box[s2];
                    const float yy1 = fmaxf(bx.x, b2.x);
                    const float xx1 = fmaxf(bx.y, b2.y);
                    const float yy2 = fminf(bx.z, b2.z);
                    const float xx2 = fminf(bx.w, b2.w);
                    const float inter = fmaxf(yy2 - yy1, 0.0f) * fmaxf(xx2 - xx1, 0.0f);
                    const float a2  = (b2.z - b2.x) * (b2.w - b2.y);
                    const float uni = ca + a2 - inter;
                    if (inter / fmaxf(uni, 1e-8f) > NMS_THR) sup = true;
                }
            }
            if (!__any_sync(0xffffffffu, sup)) {
                if (lane == 0) s_kept[s] = 1;
                kc++;
                if (kc == KK) break;    // class quota full
            }
            __syncwarp();
        }
    }
    __syncthreads();

    // ---- zero-fill all K output rows ----
    for (int k = tid; k < KK; k += NPAD) {
        const size_t bk = (size_t)b * KK + k;
        float* o = det_out + bk * 6;
        o[0] = 0.0f; o[1] = 0.0f; o[2] = 0.0f;
        o[3] = 0.0f; o[4] = 0.0f; o[5] = 0.0f;
        feat_out[bk * FF] = __int_as_float(-1);
    }
    __syncthreads();

    // ---- global kept-rank by counting; write kept rows ----
    for (int t = tid; t < V; t += NPAD) {
        if (!s_kept[t]) continue;
        const unsigned long long kv = c_kv[t];
        int r = 0;
        for (int q = 0; q < V; q++)
            r += s_kept[q] && (c_kv[q] < kv);
        if (r < KK) {
            const size_t bk = (size_t)b * KK + r;
            const float4 bx = c_box[t];
            float* o = det_out + bk * 6;
            o[0] = bx.x;
            o[1] = bx.y;
            o[2] = bx.z;
            o[3] = bx.w;
            o[4] = (float)c_cls[t];
            o[5] = c_score[t];
            feat_out[bk * FF] = __int_as_float((int)(kv & 0xFFFFFFFFu));
        }
    }
}

// =====================================================================
// K3: feature gather (empirically best config: 1 row per 256-thr CTA).
// Reads the roi index from dst[0] (written by K2), broadcasts via
// shared, then copies/zero-fills the full row (1 float4 per thread).
// =====================================================================
__global__ __launch_bounds__(256)
void feat_gather_kernel(const float* __restrict__ obj_feat,
                        float* __restrict__ feat_out)
{
    const int bk = blockIdx.x;            // b*KK + k
    const int b  = bk / KK;
    const int t  = threadIdx.x;           // 256 threads x float4 = 1024 floats

    __shared__ int sj;
    float* dst = feat_out + (size_t)bk * FF;
    if (t == 0) sj = __float_as_int(dst[0]);
    __syncthreads();
    const int j = sj;

    float4* d4 = (float4*)dst;
    if (j >= 0) {
        const float4* s4 = (const float4*)(obj_feat + ((size_t)b * BN + j) * FF);
        d4[t] = s4[t];
    } else {
        d4[t] = make_float4(0.0f, 0.0f, 0.0f, 0.0f);
    }
}

extern "C" void kernel_launch(void* const* d_in, const int* in_sizes, int n_in,
                              void* d_out, int out_size)
{
    const float* rois     = (const float*)d_in[0];
    const float* fpnclass = (const float*)d_in[1];
    const float* fpnbbox  = (const float*)d_in[2];
    const float* objfeat  = (const float*)d_in[3];
    const float* meta     = (const float*)d_in[4];

    const int B = in_sizes[0] / (BN * 4);

    float* det_out  = (float*)d_out;                         // (B, K, 6)
    float* feat_out = (float*)d_out + (size_t)B * KK * 6;    // (B, K, 1, 1, F)

    dim3 g1(NRBLK, B);
    refine_kernel<<<g1, 256>>>(rois, fpnclass, fpnbbox, meta, feat_out);
    nms_kernel<<<B, NPAD>>>(det_out, feat_out);
    feat_gather_kernel<<<B * KK, 256>>>(objfeat, feat_out);
}

// round 16
// speedup vs baseline: 1.1258x; 1.1171x over previous
#include <cuda_runtime.h>
#include <math.h>

// Problem constants (fixed by the dataset's setup_inputs)
#define BN   1000      // rois per image
#define NPAD 1024      // slot count per image (>= BN)
#define CC   81        // classes
#define KK   100       // max detections
#define FF   1024      // feature dim
#define META_STRIDE (12 + CC)

#define MIN_CONF 0.7f
#define NMS_THR  0.3f

#define RPC    8       // rois per refine CTA (one per warp)
#define NRBLK  ((BN + RPC - 1) / RPC)         // 125
#define KV_INVALID_HI 0xFFFFFFFFu             // valid kv_hi < 0x80000000

// scratch slot: 8 floats per (image, roi):
//   [0]=kv_hi bits, [1]=roi idx bits, [2]=score, [3]=cls bits, [4..7]=box
// located at feat_out + b*KK*FF + 4 + roi*8  (consumed by nms_kernel
// before any conflicting write; overwritten by gather at the end)
#define SCRATCH_OFF 4

// order-preserving float -> uint32 (ascending)
__device__ __forceinline__ unsigned int float_orderable(float f) {
    unsigned int u = __float_as_uint(f);
    return u ^ ((u >> 31) ? 0xFFFFFFFFu : 0x80000000u);
}

// =====================================================================
// K1: refine. grid = (125, B), 256 threads = 8 warps, one roi per warp.
// Softmax identity: at most one class can have prob >= 0.7 (row sums
// to 1), and any class c>=1 with prob >= 0.7 is automatically the
// unique argmax => valid. So validity + class + score come from three
// coalesced loads and three ballots — NO reduce chain. The single
// winning lane decodes/clips/writes the slot; lane 0 writes the
// invalid marker when no lane wins.
// =====================================================================
__global__ __launch_bounds__(256)
void refine_kernel(const float* __restrict__ rois,
                   const float* __restrict__ probs,
                   const float* __restrict__ deltas,
                   const float* __restrict__ meta,
                   float* __restrict__ feat_out)
{
    const int b    = blockIdx.y;
    const int i    = blockIdx.x * RPC + (threadIdx.x >> 5);
    const int lane = threadIdx.x & 31;
    if (i >= BN) return;

    const size_t gi = (size_t)b * BN + i;
    const float* pr = probs + gi * CC;

    // lanes cover classes lane, lane+32, lane+64 (coalesced)
    const float v0 = pr[lane];
    const float v1 = pr[lane + 32];                 // classes 32..63
    const float v2 = (lane + 64 < CC) ? pr[lane + 64] : -1.0f;

    const unsigned int FULL = 0xffffffffu;
    const unsigned int b0 = __ballot_sync(FULL, v0 >= MIN_CONF) & 0xFFFFFFFEu; // exclude class 0
    const unsigned int b1 = __ballot_sync(FULL, v1 >= MIN_CONF);
    const unsigned int b2 = __ballot_sync(FULL, v2 >= MIN_CONF);

    const unsigned int mybit = 1u << lane;
    const bool win0 = (b0 & mybit) != 0;
    const bool win1 = (b1 & mybit) != 0;
    const bool win2 = (b2 & mybit) != 0;

    float* scratch = feat_out + (size_t)b * KK * FF + SCRATCH_OFF;
    float2* slot = (float2*)(scratch + (size_t)i * 8);

    if (win0 | win1 | win2) {
        // this lane owns the unique >= 0.7 class for roi i
        const int   bc = win0 ? lane : (win1 ? lane + 32 : lane + 64);
        const float bv = win0 ? v0   : (win1 ? v1        : v2);

        // window from image_meta
        const float sy = meta[4] - 1.0f;
        const float sx = meta[5] - 1.0f;
        const float wy1 =  meta[(size_t)b * META_STRIDE + 7]          / sy;
        const float wx1 =  meta[(size_t)b * META_STRIDE + 8]          / sx;
        const float wy2 = (meta[(size_t)b * META_STRIDE + 9] - 1.0f)  / sy;
        const float wx2 = (meta[(size_t)b * META_STRIDE + 10] - 1.0f) / sx;

        const float4 dl = *(const float4*)(deltas + (gi * CC + bc) * 4);
        const float dy = dl.x * 0.1f;
        const float dx = dl.y * 0.1f;
        const float dh = dl.z * 0.2f;
        const float dw = dl.w * 0.2f;

        const float4 rr = *(const float4*)(rois + gi * 4);
        float y1 = rr.x, x1 = rr.y, y2 = rr.z, x2 = rr.w;
        const float h0 = y2 - y1, w0 = x2 - x1;
        const float cy = y1 + 0.5f * h0 + dy * h0;
        const float cx = x1 + 0.5f * w0 + dx * w0;
        const float hh = h0 * expf(dh);
        const float ww = w0 * expf(dw);
        y1 = cy - 0.5f * hh;
        x1 = cx - 0.5f * ww;
        y2 = y1 + hh;
        x2 = x1 + ww;
        y1 = fminf(fmaxf(y1, wy1), wy2);
        x1 = fminf(fmaxf(x1, wx1), wx2);
        y2 = fminf(fmaxf(y2, wy1), wy2);
        x2 = fminf(fmaxf(x2, wx1), wx2);

        slot[0] = make_float2(__uint_as_float(float_orderable(-bv)),
                              __uint_as_float((unsigned int)i));
        slot[1] = make_float2(bv, __int_as_float(bc));
        slot[2] = make_float2(y1, x1);
        slot[3] = make_float2(y2, x2);
    } else if ((b0 | b1 | b2) == 0u && lane == 0) {
        slot[0] = make_float2(__uint_as_float(KV_INVALID_HI), 0.0f);
    }
}

// =====================================================================
// K2: per-image NMS. grid = B, 1024 threads. Loads scratch slots,
// compacts valid candidates, resolves ordering by counting packed-kv
// comparisons (== stable argsort of reference), runs warp-per-class
// greedy NMS, writes det rows + gather index into feat row slot 0.
// =====================================================================
__global__ __launch_bounds__(NPAD)
void nms_kernel(float* __restrict__ det_out,
                float* __restrict__ feat_out)
{
    __shared__ unsigned long long c_kv[NPAD];
    __shared__ float4 c_box[NPAD];
    __shared__ float  c_score[NPAD];
    __shared__ int    c_cls[NPAD];
    __shared__ int    c_wr[NPAD];
    __shared__ int    c_list[NPAD];
    __shared__ unsigned char s_kept[NPAD];
    __shared__ int    s_ccnt[CC], s_cst[CC];
    __shared__ int    s_nv;

    const int b    = blockIdx.x;
    const int tid  = threadIdx.x;
    const int wid  = tid >> 5;
    const int lane = tid & 31;

    if (tid == 0) s_nv = 0;
    for (int c = tid; c < CC; c += NPAD) s_ccnt[c] = 0;
    s_kept[tid] = 0;
    __syncthreads();

    // ---- load scratch slots, compact valid candidates ----
    const float* scratch = feat_out + (size_t)b * KK * FF + SCRATCH_OFF;
    if (tid < BN) {
        const float2* slot = (const float2*)(scratch + (size_t)tid * 8);
        const float2 s0 = slot[0];
        const unsigned int kv_hi = __float_as_uint(s0.x);
        if (kv_hi != KV_INVALID_HI) {
            const float2 s1 = slot[1];
            const float2 s2 = slot[2];
            const float2 s3 = slot[3];
            const int t = atomicAdd(&s_nv, 1);
            c_kv[t]    = ((unsigned long long)kv_hi << 32)
                         | __float_as_uint(s0.y);
            c_score[t] = s1.x;
            c_cls[t]   = __float_as_int(s1.y);
            c_box[t]   = make_float4(s2.x, s2.y, s3.x, s3.y);
        }
    }
    __syncthreads();
    const int V = s_nv;

    // ---- within-class rank by counting ----
    for (int t = tid; t < V; t += NPAD) {
        const unsigned long long kv = c_kv[t];
        const int c = c_cls[t];
        int r = 0;
        for (int q = 0; q < V; q++)
            r += (c_cls[q] == c) && (c_kv[q] < kv);
        c_wr[t] = r;
        atomicAdd(&s_ccnt[c], 1);
    }
    __syncthreads();

    // ---- class prefix + scatter into per-class lists ----
    if (tid == 0) {
        int acc = 0;
        for (int c = 0; c < CC; c++) { s_cst[c] = acc; acc += s_ccnt[c]; }
    }
    __syncthreads();
    for (int t = tid; t < V; t += NPAD)
        c_list[s_cst[c_cls[t]] + c_wr[t]] = t;
    __syncthreads();

    // ---- per-class greedy NMS, one warp per class ----
    for (int c = wid; c < CC; c += 32) {
        const int n = s_ccnt[c];
        if (n == 0) continue;
        const int base = s_cst[c];
        int kc = 0;
        for (int t = 0; t < n; t++) {
            const int s = c_list[base + t];
            const float4 bx = c_box[s];
            const float ca = (bx.z - bx.x) * (bx.w - bx.y);

            bool sup = false;
            for (int q = lane; q < t; q += 32) {
                const int s2 = c_list[base + q];
                if (s_kept[s2]) {
                    const float4 b2 = c_box[s2];
                    const float yy1 = fmaxf(bx.x, b2.x);
                    const float xx1 = fmaxf(bx.y, b2.y);
                    const float yy2 = fminf(bx.z, b2.z);
                    const float xx2 = fminf(bx.w, b2.w);
                    const float inter = fmaxf(yy2 - yy1, 0.0f) * fmaxf(xx2 - xx1, 0.0f);
                    const float a2  = (b2.z - b2.x) * (b2.w - b2.y);
                    const float uni = ca + a2 - inter;
                    if (inter / fmaxf(uni, 1e-8f) > NMS_THR) sup = true;
                }
            }
            if (!__any_sync(0xffffffffu, sup)) {
                if (lane == 0) s_kept[s] = 1;
                kc++;
                if (kc == KK) break;    // class quota full
            }
            __syncwarp();
        }
    }
    __syncthreads();

    // ---- zero-fill all K output rows ----
    for (int k = tid; k < KK; k += NPAD) {
        const size_t bk = (size_t)b * KK + k;
        float* o = det_out + bk * 6;
        o[0] = 0.0f; o[1] = 0.0f; o[2] = 0.0f;
        o[3] = 0.0f; o[4] = 0.0f; o[5] = 0.0f;
        feat_out[bk * FF] = __int_as_float(-1);
    }
    __syncthreads();

    // ---- global kept-rank by counting; write kept rows ----
    for (int t = tid; t < V; t += NPAD) {
        if (!s_kept[t]) continue;
        const unsigned long long kv = c_kv[t];
        int r = 0;
        for (int q = 0; q < V; q++)
            r += s_kept[q] && (c_kv[q] < kv);
        if (r < KK) {
            const size_t bk = (size_t)b * KK + r;
            const float4 bx = c_box[t];
            float* o = det_out + bk * 6;
            o[0] = bx.x;
            o[1] = bx.y;
            o[2] = bx.z;
            o[3] = bx.w;
            o[4] = (float)c_cls[t];
            o[5] = c_score[t];
            feat_out[bk * FF] = __int_as_float((int)(kv & 0xFFFFFFFFu));
        }
    }
}

// =====================================================================
// K3: feature gather (empirically best config: 1 row per 256-thr CTA).
// Reads the roi index from dst[0] (written by K2), broadcasts via
// shared, then copies/zero-fills the full row (1 float4 per thread).
// =====================================================================
__global__ __launch_bounds__(256)
void feat_gather_kernel(const float* __restrict__ obj_feat,
                        float* __restrict__ feat_out)
{
    const int bk = blockIdx.x;            // b*KK + k
    const int b  = bk / KK;
    const int t  = threadIdx.x;           // 256 threads x float4 = 1024 floats

    __shared__ int sj;
    float* dst = feat_out + (size_t)bk * FF;
    if (t == 0) sj = __float_as_int(dst[0]);
    __syncthreads();
    const int j = sj;

    float4* d4 = (float4*)dst;
    if (j >= 0) {
        const float4* s4 = (const float4*)(obj_feat + ((size_t)b * BN + j) * FF);
        d4[t] = s4[t];
    } else {
        d4[t] = make_float4(0.0f, 0.0f, 0.0f, 0.0f);
    }
}

extern "C" void kernel_launch(void* const* d_in, const int* in_sizes, int n_in,
                              void* d_out, int out_size)
{
    const float* rois     = (const float*)d_in[0];
    const float* fpnclass = (const float*)d_in[1];
    const float* fpnbbox  = (const float*)d_in[2];
    const float* objfeat  = (const float*)d_in[3];
    const float* meta     = (const float*)d_in[4];

    const int B = in_sizes[0] / (BN * 4);

    float* det_out  = (float*)d_out;                         // (B, K, 6)
    float* feat_out = (float*)d_out + (size_t)B * KK * 6;    // (B, K, 1, 1, F)

    dim3 g1(NRBLK, B);
    refine_kernel<<<g1, 256>>>(rois, fpnclass, fpnbbox, meta, feat_out);
    nms_kernel<<<B, NPAD>>>(det_out, feat_out);
    feat_gather_kernel<<<B * KK, 256>>>(objfeat, feat_out);
}